// round 1
// baseline (speedup 1.0000x reference)
#include <cuda_runtime.h>
#include <math.h>

#define NA 50000
#define MM 12
#define AD 128
#define ND 64
#define FD 256
#define NROWS (NA*MM)
#define EPSV 1e-5f

// Scratch (device globals: allocation-free per harness rules)
__device__ float g_QP[(size_t)NA*512];           // [n][0:256]=Q(self)  [n][256:512]=P(nbr)
__device__ float g_gated[(size_t)NROWS*FD];      // 614 MB
__device__ float g_nbrsum[(size_t)NA*AD];
__device__ float g_sum1[FD], g_sq1[FD], g_scale1[FD], g_shift1[FD];
__device__ float g_sum2[AD], g_sq2[AD], g_scale2[AD], g_shift2[AD];
__device__ float g_cnt;

__device__ __forceinline__ float softplusf(float x){
    return fmaxf(x, 0.f) + log1pf(expf(-fabsf(x)));
}
__device__ __forceinline__ float sigmoidf(float x){
    return 1.f/(1.f + expf(-x));
}

__global__ void k_zero(){
    int t = threadIdx.x;
    if(t < FD){ g_sum1[t] = 0.f; g_sq1[t] = 0.f; }
    if(t < AD){ g_sum2[t] = 0.f; g_sq2[t] = 0.f; }
    if(t == 0) g_cnt = 0.f;
}

// ---------------------------------------------------------------------------
// K0: QP[n, 0:512] = atom[n] @ [W1 | W2]   (50000x128 @ 128x512, fp32)
// BM=64 BN=64 BK=32, 256 threads as 16x16, 4x4 microtile
// ---------------------------------------------------------------------------
__global__ __launch_bounds__(256) void k_qp(const float* __restrict__ atom,
                                            const float* __restrict__ W){
    __shared__ float As[64][32];
    __shared__ float Bs[32][64];
    int tid = threadIdx.x;
    int tx = tid & 15, ty = tid >> 4;
    int n0 = blockIdx.x * 64;
    int cb = blockIdx.y * 64;
    float acc[4][4] = {};

    for(int ks = 0; ks < 128; ks += 32){
        #pragma unroll
        for(int l = 0; l < 2; l++){
            int f4 = tid + l*256;
            int r = f4 >> 3, c = (f4 & 7) * 4;
            float4 v = make_float4(0.f,0.f,0.f,0.f);
            if(n0 + r < NA) v = *(const float4*)&atom[(size_t)(n0+r)*AD + ks + c];
            *(float4*)&As[r][c] = v;
        }
        #pragma unroll
        for(int l = 0; l < 2; l++){
            int f4 = tid + l*256;
            int k = f4 >> 4, c4 = (f4 & 15) * 4;
            int kg = ks + k, cg = cb + c4;
            float4 v;
            if(cg < 256) v = *(const float4*)&W[(size_t)kg*FD + cg];          // W1
            else         v = *(const float4*)&W[(size_t)(128+kg)*FD + (cg-256)]; // W2
            *(float4*)&Bs[k][c4] = v;
        }
        __syncthreads();
        #pragma unroll
        for(int k = 0; k < 32; k++){
            float4 bv = *(float4*)&Bs[k][tx*4];
            #pragma unroll
            for(int i = 0; i < 4; i++){
                float a = As[ty*4+i][k];
                acc[i][0] += a*bv.x; acc[i][1] += a*bv.y;
                acc[i][2] += a*bv.z; acc[i][3] += a*bv.w;
            }
        }
        __syncthreads();
    }
    #pragma unroll
    for(int i = 0; i < 4; i++){
        int n = n0 + ty*4 + i;
        if(n < NA){
            float4 v = make_float4(acc[i][0],acc[i][1],acc[i][2],acc[i][3]);
            *(float4*)&g_QP[(size_t)n*512 + cb + tx*4] = v;
        }
    }
}

// ---------------------------------------------------------------------------
// K1: gated[row] = Q[row/12] + P[idx[row]] + b + nbr[row] @ W3
//     + masked per-column sum / sumsq atomics (BN1 stats) + mask count.
// BM=64 rows, BN=256 (full), BK=32 x2. 256 threads as 32x8, 8x8 microtile.
// ---------------------------------------------------------------------------
__global__ __launch_bounds__(256,2) void k_edge(const float* __restrict__ nbr,
        const int* __restrict__ idx, const float* __restrict__ mask,
        const float* __restrict__ W, const float* __restrict__ bfc){
    __shared__ float Wt[32][256];   // reused as reduction buffer afterwards
    __shared__ float Nt[64][32];
    __shared__ int   sIdx[64];
    __shared__ float sMask[64];
    int tid = threadIdx.x;
    int tx = tid & 31, ty = tid >> 5;
    int row0 = blockIdx.x * 64;

    if(tid < 64){ sIdx[tid] = idx[row0+tid]; sMask[tid] = mask[row0+tid]; }

    float acc[8][8] = {};
    for(int ks = 0; ks < 64; ks += 32){
        #pragma unroll
        for(int l = 0; l < 2; l++){
            int f4 = tid + l*256;
            int r = f4 >> 3, c = (f4 & 7) * 4;
            *(float4*)&Nt[r][c] = *(const float4*)&nbr[(size_t)(row0+r)*ND + ks + c];
        }
        #pragma unroll
        for(int l = 0; l < 8; l++){
            int f4 = tid + l*256;
            int k = f4 >> 6, c = (f4 & 63) * 4;
            *(float4*)&Wt[k][c] = *(const float4*)&W[(size_t)(256+ks+k)*FD + c];
        }
        __syncthreads();
        #pragma unroll
        for(int k = 0; k < 32; k++){
            float4 b0 = *(float4*)&Wt[k][tx*8];
            float4 b1 = *(float4*)&Wt[k][tx*8+4];
            #pragma unroll
            for(int i = 0; i < 8; i++){
                float a = Nt[ty*8+i][k];
                acc[i][0]+=a*b0.x; acc[i][1]+=a*b0.y; acc[i][2]+=a*b0.z; acc[i][3]+=a*b0.w;
                acc[i][4]+=a*b1.x; acc[i][5]+=a*b1.y; acc[i][6]+=a*b1.z; acc[i][7]+=a*b1.w;
            }
        }
        __syncthreads();
    }

    int cbase = tx*8;
    float bv[8];
    #pragma unroll
    for(int j = 0; j < 8; j++) bv[j] = __ldg(&bfc[cbase+j]);

    float cs[8] = {}, cq[8] = {};
    #pragma unroll
    for(int i = 0; i < 8; i++){
        int r = ty*8 + i;
        int grow = row0 + r;
        int n  = grow / 12;
        int jn = sIdx[r];
        float mk = sMask[r];
        const float* qs = &g_QP[(size_t)n*512 + cbase];
        const float* qn = &g_QP[(size_t)jn*512 + 256 + cbase];
        float v[8];
        #pragma unroll
        for(int j = 0; j < 8; j++){
            float x = acc[i][j] + qs[j] + qn[j] + bv[j];
            v[j] = x;
            cs[j] += mk*x;
            cq[j] += mk*x*x;
        }
        *(float4*)&g_gated[(size_t)grow*FD + cbase]     = make_float4(v[0],v[1],v[2],v[3]);
        *(float4*)&g_gated[(size_t)grow*FD + cbase + 4] = make_float4(v[4],v[5],v[6],v[7]);
    }

    // per-block column reduction in smem (reuse Wt), then 2 atomics per column
    float* red = &Wt[0][0];
    #pragma unroll
    for(int j = 0; j < 8; j++){
        red[(cbase+j)*8 + ty]        = cs[j];
        red[2048 + (cbase+j)*8 + ty] = cq[j];
    }
    __syncthreads();
    {
        int c = tid;  // 256 threads, 256 cols
        float s = 0.f, q = 0.f;
        #pragma unroll
        for(int t = 0; t < 8; t++){ s += red[c*8+t]; q += red[2048 + c*8+t]; }
        atomicAdd(&g_sum1[c], s);
        atomicAdd(&g_sq1[c], q);
    }
    if(tid == 0){
        float c64 = 0.f;
        #pragma unroll
        for(int r = 0; r < 64; r++) c64 += sMask[r];
        atomicAdd(&g_cnt, c64);
    }
}

// ---------------------------------------------------------------------------
// K2/K4: finalize batchnorm stats into scale/shift
// ---------------------------------------------------------------------------
__global__ void k_fin1(const float* __restrict__ gamma, const float* __restrict__ beta){
    int c = threadIdx.x;
    float cnt = g_cnt;
    float m = g_sum1[c] / cnt;
    float v = g_sq1[c] / cnt - m*m;
    float r = rsqrtf(v + EPSV);
    float sc = gamma[c] * r;
    g_scale1[c] = sc;
    g_shift1[c] = beta[c] - m*sc;
}

__global__ void k_fin2(const float* __restrict__ gamma, const float* __restrict__ beta){
    int c = threadIdx.x;
    float m = g_sum2[c] / (float)NA;
    float v = g_sq2[c] / (float)NA - m*m;
    float r = rsqrtf(v + EPSV);
    float sc = gamma[c] * r;
    g_scale2[c] = sc;
    g_shift2[c] = beta[c] - m*sc;
}

// ---------------------------------------------------------------------------
// K3: normalize (masked rows only matter), sigmoid(filter)*softplus(core)*mask,
//     sum over m -> nbr_sumed[n], accumulate BN2 stats.
// One block = 16 atoms, 128 threads = 128 feature columns.
// ---------------------------------------------------------------------------
__global__ __launch_bounds__(128) void k_pool(const float* __restrict__ mask){
    int c  = threadIdx.x;
    int n0 = blockIdx.x * 16;
    float s1  = g_scale1[c],      h1  = g_shift1[c];
    float s1b = g_scale1[c+128],  h1b = g_shift1[c+128];
    float ls = 0.f, lq = 0.f;
    for(int a = 0; a < 16; a++){
        int n = n0 + a;
        float acc = 0.f;
        #pragma unroll
        for(int m = 0; m < MM; m++){
            int row = n*MM + m;
            float mk = __ldg(&mask[row]);
            if(mk != 0.f){   // warp-uniform: skip ~half the gated reads
                float f = g_gated[(size_t)row*FD + c]       * s1  + h1;
                float g = g_gated[(size_t)row*FD + 128 + c] * s1b + h1b;
                acc += mk * sigmoidf(f) * softplusf(g);
            }
        }
        g_nbrsum[(size_t)n*AD + c] = acc;
        ls += acc; lq += acc*acc;
    }
    atomicAdd(&g_sum2[c], ls);
    atomicAdd(&g_sq2[c], lq);
}

// ---------------------------------------------------------------------------
// K5: out = softplus(atom + BN2(nbr_sumed))
// ---------------------------------------------------------------------------
__global__ void k_out(const float* __restrict__ atom, float* __restrict__ out){
    int i = blockIdx.x*blockDim.x + threadIdx.x;
    if(i < NA*AD){
        int c = i & 127;
        float x = atom[i] + g_nbrsum[i]*g_scale2[c] + g_shift2[c];
        out[i] = softplusf(x);
    }
}

extern "C" void kernel_launch(void* const* d_in, const int* in_sizes, int n_in,
                              void* d_out, int out_size){
    const float* atom = (const float*)d_in[0];
    const float* nbr  = (const float*)d_in[1];
    const int*   idx  = (const int*)  d_in[2];
    const float* mask = (const float*)d_in[3];
    const float* W    = (const float*)d_in[4];
    const float* bfc  = (const float*)d_in[5];
    const float* g1   = (const float*)d_in[6];
    const float* be1  = (const float*)d_in[7];
    const float* g2   = (const float*)d_in[8];
    const float* be2  = (const float*)d_in[9];
    float* out = (float*)d_out;

    k_zero<<<1, 256>>>();
    dim3 gq((NA + 63)/64, 8);
    k_qp<<<gq, 256>>>(atom, W);
    k_edge<<<NROWS/64, 256>>>(nbr, idx, mask, W, bfc);
    k_fin1<<<1, 256>>>(g1, be1);
    k_pool<<<NA/16, 128>>>(mask);
    k_fin2<<<1, 128>>>(g2, be2);
    k_out<<<(NA*AD + 255)/256, 256>>>(atom, out);
}

// round 5
// speedup vs baseline: 1.3633x; 1.3633x over previous
#include <cuda_runtime.h>
#include <cuda_bf16.h>
#include <math.h>
#include <stdint.h>

#define NA 50000
#define MM 12
#define AD 128
#define ND 64
#define FD 256
#define NROWS (NA*MM)
#define EPSV 1e-5f
#define PADE 72       // k_edge smem row pad (bf16 elements)
#define PADQ 136      // k_qp  smem row pad

// Scratch (device globals: allocation-free per harness rules)
__device__ float g_QP[(size_t)NA*512];           // [n][0:256]=Q  [n][256:512]=P
__device__ float g_gated[(size_t)NROWS*FD];      // 614 MB
__device__ float g_nbrsum[(size_t)NA*AD];
__device__ float g_sum1[FD], g_sq1[FD], g_scale1[FD], g_shift1[FD];
__device__ float g_sum2[AD], g_sq2[AD], g_scale2[AD], g_shift2[AD];
__device__ float g_cnt;
// Pre-split bf16 weights, K-contiguous rows with pad
__device__ __align__(16) __nv_bfloat16 g_Bh[256*PADE];   // W3^T [256 n][64 k] hi
__device__ __align__(16) __nv_bfloat16 g_Bl[256*PADE];   // lo
__device__ __align__(16) __nv_bfloat16 g_Wh[512*PADQ];   // [W1|W2]^T [512 n][128 k] hi
__device__ __align__(16) __nv_bfloat16 g_Wl[512*PADQ];   // lo

__device__ __forceinline__ float softplusf(float x){
    return fmaxf(x, 0.f) + log1pf(expf(-fabsf(x)));
}
__device__ __forceinline__ float sigmoidf(float x){
    return 1.f/(1.f + expf(-x));
}
__device__ __forceinline__ float warp_sum(float v){
    #pragma unroll
    for(int o = 16; o > 0; o >>= 1) v += __shfl_xor_sync(0xffffffffu, v, o);
    return v;
}
__device__ __forceinline__ void mma_bf16(float* d,
        uint32_t a0, uint32_t a1, uint32_t a2, uint32_t a3,
        uint32_t b0, uint32_t b1){
    asm volatile(
        "mma.sync.aligned.m16n8k16.row.col.f32.bf16.bf16.f32 "
        "{%0,%1,%2,%3}, {%4,%5,%6,%7}, {%8,%9}, {%0,%1,%2,%3};"
        : "+f"(d[0]), "+f"(d[1]), "+f"(d[2]), "+f"(d[3])
        : "r"(a0), "r"(a1), "r"(a2), "r"(a3), "r"(b0), "r"(b1));
}
__device__ __forceinline__ void split_bf16(float x, __nv_bfloat16& h, __nv_bfloat16& l){
    h = __float2bfloat16_rn(x);
    l = __float2bfloat16_rn(x - __bfloat162float(h));
}

__global__ void k_zero(){
    int t = threadIdx.x;
    if(t < FD){ g_sum1[t] = 0.f; g_sq1[t] = 0.f; }
    if(t < AD){ g_sum2[t] = 0.f; g_sq2[t] = 0.f; }
    if(t == 0) g_cnt = 0.f;
}

// ---------------------------------------------------------------------------
// Prep: split weights into transposed bf16 hi/lo with padded K-contiguous rows
// ---------------------------------------------------------------------------
__global__ void k_prep(const float* __restrict__ W){
    int t = threadIdx.x;  // 256
    // edge B: [256 n][64 k] from W rows 256..319
    for(int k = 0; k < 64; k++){
        float w = W[(size_t)(256+k)*FD + t];
        __nv_bfloat16 h, l; split_bf16(w, h, l);
        g_Bh[t*PADE + k] = h;
        g_Bl[t*PADE + k] = l;
    }
    // qp B: [512 n][128 k]: n<256 -> W1 (W rows 0..127), n>=256 -> W2 (W rows 128..255)
    for(int half = 0; half < 2; half++){
        int n = t + half*256;
        for(int k = 0; k < 128; k++){
            float w = (n < 256) ? W[(size_t)k*FD + n]
                                : W[(size_t)(128+k)*FD + (n-256)];
            __nv_bfloat16 h, l; split_bf16(w, h, l);
            g_Wh[n*PADQ + k] = h;
            g_Wl[n*PADQ + k] = l;
        }
    }
}

// ---------------------------------------------------------------------------
// K0 (mma.sync): QP[n, cb:cb+128] = atom[n] @ [W1|W2][:, cb:cb+128]
// block: 256 thr (8 warps), tile 128 rows x 128 cols, K=128 (8 k16 steps)
// ---------------------------------------------------------------------------
#define SMEM_QP 139264
__global__ __launch_bounds__(256) void k_qp_mma(const float* __restrict__ atom){
    extern __shared__ char smem[];
    __nv_bfloat16* Ah = (__nv_bfloat16*)(smem);
    __nv_bfloat16* Al = (__nv_bfloat16*)(smem + 34816);
    __nv_bfloat16* Bh = (__nv_bfloat16*)(smem + 69632);
    __nv_bfloat16* Bl = (__nv_bfloat16*)(smem + 104448);
    int tid = threadIdx.x, wid = tid >> 5, lane = tid & 31;
    int n0 = blockIdx.x * 128;
    int cb = blockIdx.y * 128;

    // B tile copy: 128 rows x PADQ bf16 = 34816 B = 2176 uint4
    {
        const uint4* srcH = (const uint4*)(g_Wh + (size_t)cb*PADQ);
        const uint4* srcL = (const uint4*)(g_Wl + (size_t)cb*PADQ);
        uint4* dH = (uint4*)Bh;
        uint4* dL = (uint4*)Bl;
        #pragma unroll
        for(int i = 0; i < 9; i++){
            int f = tid + i*256;
            if(f < 2176){ dH[f] = srcH[f]; dL[f] = srcL[f]; }
        }
    }
    // A tile: 128 rows x 128 floats -> hi/lo bf16
    #pragma unroll
    for(int i = 0; i < 16; i++){
        int f = tid + i*256;
        int row = f >> 5, j = f & 31;
        int grow = n0 + row;
        float4 v = make_float4(0.f,0.f,0.f,0.f);
        if(grow < NA) v = *(const float4*)&atom[(size_t)grow*AD + j*4];
        __nv_bfloat16 h0,l0,h1,l1,h2,l2,h3,l3;
        split_bf16(v.x,h0,l0); split_bf16(v.y,h1,l1);
        split_bf16(v.z,h2,l2); split_bf16(v.w,h3,l3);
        int base = row*PADQ + j*4;
        __nv_bfloat162 hp0; hp0.x=h0; hp0.y=h1;
        __nv_bfloat162 hp1; hp1.x=h2; hp1.y=h3;
        __nv_bfloat162 lp0; lp0.x=l0; lp0.y=l1;
        __nv_bfloat162 lp1; lp1.x=l2; lp1.y=l3;
        *(__nv_bfloat162*)&Ah[base]   = hp0;
        *(__nv_bfloat162*)&Ah[base+2] = hp1;
        *(__nv_bfloat162*)&Al[base]   = lp0;
        *(__nv_bfloat162*)&Al[base+2] = lp1;
    }
    __syncthreads();

    int wrow = wid * 16;
    float acc[16][4];
    #pragma unroll
    for(int t = 0; t < 16; t++){ acc[t][0]=0.f; acc[t][1]=0.f; acc[t][2]=0.f; acc[t][3]=0.f; }

    #pragma unroll
    for(int ks = 0; ks < 8; ks++){
        int k0 = ks*16;
        int ar = wrow + (lane>>2);
        int ac = k0 + (lane&3)*2;
        uint32_t ah0 = *(uint32_t*)&Ah[ar*PADQ+ac];
        uint32_t ah1 = *(uint32_t*)&Ah[(ar+8)*PADQ+ac];
        uint32_t ah2 = *(uint32_t*)&Ah[ar*PADQ+ac+8];
        uint32_t ah3 = *(uint32_t*)&Ah[(ar+8)*PADQ+ac+8];
        uint32_t al0 = *(uint32_t*)&Al[ar*PADQ+ac];
        uint32_t al1 = *(uint32_t*)&Al[(ar+8)*PADQ+ac];
        uint32_t al2 = *(uint32_t*)&Al[ar*PADQ+ac+8];
        uint32_t al3 = *(uint32_t*)&Al[(ar+8)*PADQ+ac+8];
        #pragma unroll
        for(int t = 0; t < 16; t++){
            int br = t*8 + (lane>>2);
            int bc = k0 + (lane&3)*2;
            uint32_t bh0 = *(uint32_t*)&Bh[br*PADQ+bc];
            uint32_t bh1 = *(uint32_t*)&Bh[br*PADQ+bc+8];
            uint32_t bl0 = *(uint32_t*)&Bl[br*PADQ+bc];
            uint32_t bl1 = *(uint32_t*)&Bl[br*PADQ+bc+8];
            mma_bf16(acc[t], ah0,ah1,ah2,ah3, bh0,bh1);
            mma_bf16(acc[t], ah0,ah1,ah2,ah3, bl0,bl1);
            mma_bf16(acc[t], al0,al1,al2,al3, bh0,bh1);
        }
    }

    int r0 = n0 + wrow + (lane>>2);
    int r1 = r0 + 8;
    #pragma unroll
    for(int t = 0; t < 16; t++){
        int c0 = cb + t*8 + (lane&3)*2;
        if(r0 < NA) *(float2*)&g_QP[(size_t)r0*512 + c0] = make_float2(acc[t][0], acc[t][1]);
        if(r1 < NA) *(float2*)&g_QP[(size_t)r1*512 + c0] = make_float2(acc[t][2], acc[t][3]);
    }
}

// ---------------------------------------------------------------------------
// K1 (mma.sync): gated[row] = nbr[row]@W3^T + Q[row/12] + P[idx[row]] + b
// + fused masked BN1 column stats.
// block: 256 thr (8 warps), tile 128 rows x 256 cols (2 passes of 128), K=64.
// ---------------------------------------------------------------------------
#define SMEM_EDGE 129024
__global__ __launch_bounds__(256) void k_edge_mma(const float* __restrict__ nbr,
        const int* __restrict__ idx, const float* __restrict__ mask,
        const float* __restrict__ bfc){
    extern __shared__ char smem[];
    int*   sIdx  = (int*)  (smem);            // 512
    float* sMask = (float*)(smem + 512);      // 512
    float* sBias = (float*)(smem + 1024);     // 1024
    float* sSw   = (float*)(smem + 2048);     // 8 warps x 256 = 8KB
    float* sQw   = (float*)(smem + 10240);    // 8KB
    __nv_bfloat16* Ah = (__nv_bfloat16*)(smem + 18432);  // 128 x PADE
    __nv_bfloat16* Al = (__nv_bfloat16*)(smem + 36864);
    __nv_bfloat16* Bh = (__nv_bfloat16*)(smem + 55296);  // 256 x PADE
    __nv_bfloat16* Bl = (__nv_bfloat16*)(smem + 92160);
    int tid = threadIdx.x, wid = tid >> 5, lane = tid & 31;
    int row0 = blockIdx.x * 128;

    if(tid < 128){
        int grow = row0 + tid;
        bool v = grow < NROWS;
        sIdx[tid]  = v ? idx[grow]  : 0;
        sMask[tid] = v ? mask[grow] : 0.f;
    }
    sBias[tid] = bfc[tid];
    #pragma unroll
    for(int i = 0; i < 8; i++){ sSw[tid + i*256] = 0.f; sQw[tid + i*256] = 0.f; }

    // B copy: 256 x PADE bf16 = 36864 B = 2304 uint4 (9 iters exact)
    {
        const uint4* srcH = (const uint4*)g_Bh;
        const uint4* srcL = (const uint4*)g_Bl;
        uint4* dH = (uint4*)Bh;
        uint4* dL = (uint4*)Bl;
        #pragma unroll
        for(int i = 0; i < 9; i++){
            int f = tid + i*256;
            dH[f] = srcH[f];
            dL[f] = srcL[f];
        }
    }
    // A: 128 rows x 64 floats -> hi/lo
    #pragma unroll
    for(int i = 0; i < 8; i++){
        int f = tid + i*256;
        int row = f >> 4, j = f & 15;
        int grow = row0 + row;
        float4 v = make_float4(0.f,0.f,0.f,0.f);
        if(grow < NROWS) v = *(const float4*)&nbr[(size_t)grow*ND + j*4];
        __nv_bfloat16 h0,l0,h1,l1,h2,l2,h3,l3;
        split_bf16(v.x,h0,l0); split_bf16(v.y,h1,l1);
        split_bf16(v.z,h2,l2); split_bf16(v.w,h3,l3);
        int base = row*PADE + j*4;
        __nv_bfloat162 hp0; hp0.x=h0; hp0.y=h1;
        __nv_bfloat162 hp1; hp1.x=h2; hp1.y=h3;
        __nv_bfloat162 lp0; lp0.x=l0; lp0.y=l1;
        __nv_bfloat162 lp1; lp1.x=l2; lp1.y=l3;
        *(__nv_bfloat162*)&Ah[base]   = hp0;
        *(__nv_bfloat162*)&Ah[base+2] = hp1;
        *(__nv_bfloat162*)&Al[base]   = lp0;
        *(__nv_bfloat162*)&Al[base+2] = lp1;
    }
    __syncthreads();

    int wrow = wid * 16;
    int lr0 = wrow + (lane>>2), lr1 = lr0 + 8;
    int gr0 = row0 + lr0, gr1 = row0 + lr1;
    bool v0 = gr0 < NROWS, v1 = gr1 < NROWS;
    float mk0 = sMask[lr0], mk1 = sMask[lr1];
    const float* Q0 = g_QP + (size_t)(v0 ? gr0/MM : 0)*512;
    const float* Q1 = g_QP + (size_t)(v1 ? gr1/MM : 0)*512;
    const float* P0 = g_QP + (size_t)sIdx[lr0]*512 + 256;
    const float* P1 = g_QP + (size_t)sIdx[lr1]*512 + 256;
    float* go0 = g_gated + (size_t)gr0*FD;
    float* go1 = g_gated + (size_t)gr1*FD;

    for(int pass = 0; pass < 2; pass++){
        int npass = pass*128;
        float acc[16][4];
        #pragma unroll
        for(int t = 0; t < 16; t++){ acc[t][0]=0.f; acc[t][1]=0.f; acc[t][2]=0.f; acc[t][3]=0.f; }

        #pragma unroll
        for(int ks = 0; ks < 4; ks++){
            int k0 = ks*16;
            int ar = wrow + (lane>>2);
            int ac = k0 + (lane&3)*2;
            uint32_t ah0 = *(uint32_t*)&Ah[ar*PADE+ac];
            uint32_t ah1 = *(uint32_t*)&Ah[(ar+8)*PADE+ac];
            uint32_t ah2 = *(uint32_t*)&Ah[ar*PADE+ac+8];
            uint32_t ah3 = *(uint32_t*)&Ah[(ar+8)*PADE+ac+8];
            uint32_t al0 = *(uint32_t*)&Al[ar*PADE+ac];
            uint32_t al1 = *(uint32_t*)&Al[(ar+8)*PADE+ac];
            uint32_t al2 = *(uint32_t*)&Al[ar*PADE+ac+8];
            uint32_t al3 = *(uint32_t*)&Al[(ar+8)*PADE+ac+8];
            #pragma unroll
            for(int t = 0; t < 16; t++){
                int br = npass + t*8 + (lane>>2);
                int bc = k0 + (lane&3)*2;
                uint32_t bh0 = *(uint32_t*)&Bh[br*PADE+bc];
                uint32_t bh1 = *(uint32_t*)&Bh[br*PADE+bc+8];
                uint32_t bl0 = *(uint32_t*)&Bl[br*PADE+bc];
                uint32_t bl1 = *(uint32_t*)&Bl[br*PADE+bc+8];
                mma_bf16(acc[t], ah0,ah1,ah2,ah3, bh0,bh1);
                mma_bf16(acc[t], ah0,ah1,ah2,ah3, bl0,bl1);
                mma_bf16(acc[t], al0,al1,al2,al3, bh0,bh1);
            }
        }

        // epilogue: add Q/P/bias, write gated, fused masked stats
        #pragma unroll
        for(int t = 0; t < 16; t++){
            int c0 = npass + t*8 + (lane&3)*2;
            float2 q0 = *(const float2*)(Q0 + c0);
            float2 p0 = *(const float2*)(P0 + c0);
            float2 q1 = *(const float2*)(Q1 + c0);
            float2 p1 = *(const float2*)(P1 + c0);
            float2 bb = *(const float2*)(sBias + c0);
            float v00 = acc[t][0] + q0.x + p0.x + bb.x;
            float v01 = acc[t][1] + q0.y + p0.y + bb.y;
            float v10 = acc[t][2] + q1.x + p1.x + bb.x;
            float v11 = acc[t][3] + q1.y + p1.y + bb.y;
            if(v0) *(float2*)(go0 + c0) = make_float2(v00, v01);
            if(v1) *(float2*)(go1 + c0) = make_float2(v10, v11);
            float sA = mk0*v00 + mk1*v10;
            float sB = mk0*v01 + mk1*v11;
            float qA = mk0*v00*v00 + mk1*v10*v10;
            float qB = mk0*v01*v01 + mk1*v11*v11;
            #pragma unroll
            for(int o = 4; o < 32; o <<= 1){
                sA += __shfl_xor_sync(0xffffffffu, sA, o);
                sB += __shfl_xor_sync(0xffffffffu, sB, o);
                qA += __shfl_xor_sync(0xffffffffu, qA, o);
                qB += __shfl_xor_sync(0xffffffffu, qB, o);
            }
            if((lane>>2) == 0){
                int c = npass + t*8 + (lane<<1);
                sSw[(wid<<8)+c]   += sA;
                sSw[(wid<<8)+c+1] += sB;
                sQw[(wid<<8)+c]   += qA;
                sQw[(wid<<8)+c+1] += qB;
            }
        }
    }
    __syncthreads();

    {
        float s = 0.f, q = 0.f;
        #pragma unroll
        for(int w = 0; w < 8; w++){ s += sSw[w*256 + tid]; q += sQw[w*256 + tid]; }
        atomicAdd(&g_sum1[tid], s);
        atomicAdd(&g_sq1[tid], q);
    }
    if(wid == 0){
        float v = sMask[lane] + sMask[lane+32] + sMask[lane+64] + sMask[lane+96];
        v = warp_sum(v);
        if(lane == 0) atomicAdd(&g_cnt, v);
    }
}

// ---------------------------------------------------------------------------
// Finalize batchnorm stats into scale/shift
// ---------------------------------------------------------------------------
__global__ void k_fin1(const float* __restrict__ gamma, const float* __restrict__ beta){
    int c = threadIdx.x;
    float cnt = g_cnt;
    float m = g_sum1[c] / cnt;
    float v = g_sq1[c] / cnt - m*m;
    float r = rsqrtf(v + EPSV);
    float sc = gamma[c] * r;
    g_scale1[c] = sc;
    g_shift1[c] = beta[c] - m*sc;
}

__global__ void k_fin2(const float* __restrict__ gamma, const float* __restrict__ beta){
    int c = threadIdx.x;
    float m = g_sum2[c] / (float)NA;
    float v = g_sq2[c] / (float)NA - m*m;
    float r = rsqrtf(v + EPSV);
    float sc = gamma[c] * r;
    g_scale2[c] = sc;
    g_shift2[c] = beta[c] - m*sc;
}

// ---------------------------------------------------------------------------
// Pool: normalize masked rows, sigmoid(filter)*softplus(core)*mask, sum over m.
// ---------------------------------------------------------------------------
__global__ __launch_bounds__(128) void k_pool(const float* __restrict__ mask){
    int c  = threadIdx.x;
    int n0 = blockIdx.x * 16;
    float s1  = g_scale1[c],      h1  = g_shift1[c];
    float s1b = g_scale1[c+128],  h1b = g_shift1[c+128];
    float ls = 0.f, lq = 0.f;
    for(int a = 0; a < 16; a++){
        int n = n0 + a;
        float acc = 0.f;
        #pragma unroll
        for(int m = 0; m < MM; m++){
            int row = n*MM + m;
            float mk = __ldg(&mask[row]);
            if(mk != 0.f){
                float f = g_gated[(size_t)row*FD + c]       * s1  + h1;
                float g = g_gated[(size_t)row*FD + 128 + c] * s1b + h1b;
                acc += mk * sigmoidf(f) * softplusf(g);
            }
        }
        g_nbrsum[(size_t)n*AD + c] = acc;
        ls += acc; lq += acc*acc;
    }
    atomicAdd(&g_sum2[c], ls);
    atomicAdd(&g_sq2[c], lq);
}

__global__ void k_out(const float* __restrict__ atom, float* __restrict__ out){
    int i = blockIdx.x*blockDim.x + threadIdx.x;
    if(i < NA*AD){
        int c = i & 127;
        float x = atom[i] + g_nbrsum[i]*g_scale2[c] + g_shift2[c];
        out[i] = softplusf(x);
    }
}

extern "C" void kernel_launch(void* const* d_in, const int* in_sizes, int n_in,
                              void* d_out, int out_size){
    const float* atom = (const float*)d_in[0];
    const float* nbr  = (const float*)d_in[1];
    const int*   idx  = (const int*)  d_in[2];
    const float* mask = (const float*)d_in[3];
    const float* W    = (const float*)d_in[4];
    const float* bfc  = (const float*)d_in[5];
    const float* g1   = (const float*)d_in[6];
    const float* be1  = (const float*)d_in[7];
    const float* g2   = (const float*)d_in[8];
    const float* be2  = (const float*)d_in[9];
    float* out = (float*)d_out;

    cudaFuncSetAttribute(k_qp_mma,   cudaFuncAttributeMaxDynamicSharedMemorySize, SMEM_QP);
    cudaFuncSetAttribute(k_edge_mma, cudaFuncAttributeMaxDynamicSharedMemorySize, SMEM_EDGE);

    k_zero<<<1, 256>>>();
    k_prep<<<1, 256>>>(W);
    k_qp_mma<<<dim3((NA+127)/128, 4), 256, SMEM_QP>>>(atom);
    k_edge_mma<<<(NROWS+127)/128, 256, SMEM_EDGE>>>(nbr, idx, mask, bfc);
    k_fin1<<<1, 256>>>(g1, be1);
    k_pool<<<NA/16, 128>>>(mask);
    k_fin2<<<1, 128>>>(g2, be2);
    k_out<<<(NA*AD+255)/256, 256>>>(atom, out);
}